// round 8
// baseline (speedup 1.0000x reference)
#include <cuda_runtime.h>
#include <cuda_bf16.h>
#include <math.h>
#include <stdint.h>

#define BB   2
#define SS   2048
#define HH   2048
#define NHD  16
#define HDD  128
#define WW   512
#define BSZ  (BB*SS)          // 4096 rows

#define NEG_INF (__int_as_float(0xff800000u))

// -------- scratch (static device globals; no dynamic allocation) --------
__device__ __nv_bfloat16 g_yh [BSZ*HH];   // layernorm out, hi
__device__ __nv_bfloat16 g_yl [BSZ*HH];   // layernorm out, lo
__device__ __nv_bfloat16 g_wqh[HH*HH], g_wql[HH*HH];
__device__ __nv_bfloat16 g_wkh[HH*HH], g_wkl[HH*HH];
__device__ __nv_bfloat16 g_wvh[HH*HH], g_wvl[HH*HH];
__device__ __nv_bfloat16 g_woh[HH*HH], g_wol[HH*HH];
__device__ __nv_bfloat16 g_qh[BSZ*HH], g_ql[BSZ*HH];   // [B,NH,S,HD] bf16 hi/lo (q pre-scaled)
__device__ __nv_bfloat16 g_kh[BSZ*HH], g_kl[BSZ*HH];
__device__ __nv_bfloat16 g_vh[BSZ*HH], g_vl[BSZ*HH];
__device__ __nv_bfloat16 g_aoh[BSZ*HH];   // attn out hi  [B,S,NH,HD]
__device__ __nv_bfloat16 g_aol[BSZ*HH];   // attn out lo

// ======================= PTX helpers (compute_100-safe only) =======================
__device__ __forceinline__ uint32_t smem_u32(const void* p) {
    uint32_t a;
    asm("{ .reg .u64 t; cvta.to.shared.u64 t, %1; cvt.u32.u64 %0, t; }" : "=r"(a) : "l"(p));
    return a;
}

__device__ __forceinline__ void cp_async16(uint32_t saddr, const void* gptr) {
    asm volatile("cp.async.cg.shared.global [%0], [%1], 16;" :: "r"(saddr), "l"(gptr));
}
__device__ __forceinline__ void cp_commit() { asm volatile("cp.async.commit_group;"); }
template<int N>
__device__ __forceinline__ void cp_wait() { asm volatile("cp.async.wait_group %0;" :: "n"(N)); }

__device__ __forceinline__ void ldm_x4(uint32_t& r0, uint32_t& r1, uint32_t& r2, uint32_t& r3,
                                       uint32_t addr) {
    asm volatile("ldmatrix.sync.aligned.m8n8.x4.shared.b16 {%0,%1,%2,%3}, [%4];"
                 : "=r"(r0), "=r"(r1), "=r"(r2), "=r"(r3) : "r"(addr));
}
__device__ __forceinline__ void ldm_x4t(uint32_t& r0, uint32_t& r1, uint32_t& r2, uint32_t& r3,
                                        uint32_t addr) {
    asm volatile("ldmatrix.sync.aligned.m8n8.x4.trans.shared.b16 {%0,%1,%2,%3}, [%4];"
                 : "=r"(r0), "=r"(r1), "=r"(r2), "=r"(r3) : "r"(addr));
}

__device__ __forceinline__ void mma16816(float* c, const uint32_t* a, const uint32_t* b) {
    asm volatile("mma.sync.aligned.m16n8k16.row.col.f32.bf16.bf16.f32 "
                 "{%0,%1,%2,%3}, {%4,%5,%6,%7}, {%8,%9}, {%0,%1,%2,%3};"
                 : "+f"(c[0]), "+f"(c[1]), "+f"(c[2]), "+f"(c[3])
                 : "r"(a[0]), "r"(a[1]), "r"(a[2]), "r"(a[3]), "r"(b[0]), "r"(b[1]));
}

__device__ __forceinline__ uint32_t pack_bf16(float a, float b) {
    const __nv_bfloat16 ba = __float2bfloat16(a), bb = __float2bfloat16(b);
    return (uint32_t)(*(const uint16_t*)&ba) | ((uint32_t)(*(const uint16_t*)&bb) << 16);
}

// ======================= LayerNorm (emits bf16 hi/lo split) =======================
__device__ __forceinline__ float block_sum_2048(float s) {
    __shared__ float ws[8];
    const int lane = threadIdx.x & 31, wid = threadIdx.x >> 5;
#pragma unroll
    for (int o = 16; o > 0; o >>= 1) s += __shfl_xor_sync(0xffffffffu, s, o);
    __syncthreads();
    if (lane == 0) ws[wid] = s;
    __syncthreads();
    float t = ws[0];
#pragma unroll
    for (int i = 1; i < 8; i++) t += ws[i];
    return t;
}

__global__ void __launch_bounds__(256) ln_kernel(const float* __restrict__ x,
                                                 const float* __restrict__ gamma,
                                                 const float* __restrict__ beta,
                                                 __nv_bfloat16* __restrict__ yh,
                                                 __nv_bfloat16* __restrict__ yl)
{
    const int row = blockIdx.x;
    const int tid = threadIdx.x;
    const float* xr = x + (size_t)row * HH;
    float v[8];
#pragma unroll
    for (int i = 0; i < 8; i++) v[i] = xr[tid + i * 256];
    float s = 0.f;
#pragma unroll
    for (int i = 0; i < 8; i++) s += v[i];
    const float mu = block_sum_2048(s) * (1.0f / HH);
    float sq = 0.f;
#pragma unroll
    for (int i = 0; i < 8; i++) { float d = v[i] - mu; sq += d * d; }
    const float var = block_sum_2048(sq) * (1.0f / HH);
    const float rs = rsqrtf(var + 1e-6f);
#pragma unroll
    for (int i = 0; i < 8; i++) {
        const int c = tid + i * 256;
        const float val = (v[i] - mu) * rs * gamma[c] + beta[c];
        const __nv_bfloat16 h = __float2bfloat16(val);
        yh[(size_t)row * HH + c] = h;
        yl[(size_t)row * HH + c] = __float2bfloat16(val - __bfloat162float(h));
    }
}

// ============ Merged weight transpose + bf16 split: 4 weights in one launch ============
__global__ void __launch_bounds__(256) wsplit_all(
    const float* __restrict__ w0, const float* __restrict__ w1,
    const float* __restrict__ w2, const float* __restrict__ w3,
    __nv_bfloat16* __restrict__ h0, __nv_bfloat16* __restrict__ l0,
    __nv_bfloat16* __restrict__ h1, __nv_bfloat16* __restrict__ l1,
    __nv_bfloat16* __restrict__ h2, __nv_bfloat16* __restrict__ l2,
    __nv_bfloat16* __restrict__ h3, __nv_bfloat16* __restrict__ l3)
{
    const int z = blockIdx.z;
    const float* W = (z == 0) ? w0 : (z == 1) ? w1 : (z == 2) ? w2 : w3;
    __nv_bfloat16* Wh = (z == 0) ? h0 : (z == 1) ? h1 : (z == 2) ? h2 : h3;
    __nv_bfloat16* Wl = (z == 0) ? l0 : (z == 1) ? l1 : (z == 2) ? l2 : l3;

    __shared__ float t[32][33];
    const int tx = threadIdx.x & 31, ty = threadIdx.x >> 5;
    const int n = blockIdx.x * 32 + tx;
#pragma unroll
    for (int i = 0; i < 4; i++) {
        const int k = blockIdx.y * 32 + ty + i * 8;
        t[ty + i * 8][tx] = W[(size_t)k * HH + n];
    }
    __syncthreads();
#pragma unroll
    for (int i = 0; i < 4; i++) {
        const int nn = blockIdx.x * 32 + ty + i * 8;
        const int kk = blockIdx.y * 32 + tx;
        const float v = t[tx][ty + i * 8];
        const __nv_bfloat16 h = __float2bfloat16(v);
        Wh[(size_t)nn * HH + kk] = h;
        Wl[(size_t)nn * HH + kk] = __float2bfloat16(v - __bfloat162float(h));
    }
}

// ======================= mma.sync GEMM core (BM=256, BN=128, BK=32) =======================
#define GQ_ROWB   80
#define GQ_AH     0
#define GQ_AL     (256 * GQ_ROWB)              // 20480
#define GQ_BH     (2 * 256 * GQ_ROWB)          // 40960
#define GQ_BL     (GQ_BH + 128 * GQ_ROWB)      // 51200
#define GQ_STAGE  (GQ_BL + 128 * GQ_ROWB)      // 61440
#define GQ_SMEM   (2 * GQ_STAGE)               // 122880

__device__ __forceinline__ void gemm_load_chunk(
    uint32_t sstage, int k0, int m0, int n0, int tid,
    const __nv_bfloat16* __restrict__ Ah, const __nv_bfloat16* __restrict__ Al,
    const __nv_bfloat16* __restrict__ Bh, const __nv_bfloat16* __restrict__ Bl)
{
#pragma unroll
    for (int j = 0; j < 12; ++j) {
        const int idx = tid + j * 256;     // 0..3071
        const int r = idx >> 2, c16 = idx & 3;
        const __nv_bfloat16* src;
        uint32_t sb; int lrow, grow;
        if (r < 256)      { src = Ah; sb = GQ_AH; lrow = r;       grow = m0 + lrow; }
        else if (r < 512) { src = Al; sb = GQ_AL; lrow = r - 256; grow = m0 + lrow; }
        else if (r < 640) { src = Bh; sb = GQ_BH; lrow = r - 512; grow = n0 + lrow; }
        else              { src = Bl; sb = GQ_BL; lrow = r - 640; grow = n0 + lrow; }
        cp_async16(sstage + sb + lrow * GQ_ROWB + c16 * 16,
                   src + (size_t)grow * HH + k0 + c16 * 8);
    }
    cp_commit();
}

// mainloop producing acc[4][8][4] for a 256x128 tile (8 warps, warp tile 64x64)
__device__ __forceinline__ void gemm_core(
    uint32_t sbase, int m0, int n0, int tid,
    const __nv_bfloat16* __restrict__ Ah, const __nv_bfloat16* __restrict__ Al,
    const __nv_bfloat16* __restrict__ Bh, const __nv_bfloat16* __restrict__ Bl,
    float acc[4][8][4])
{
    const int wid = tid >> 5, lane = tid & 31;
    const int m_w = (wid >> 1) * 64, n_w = (wid & 1) * 64;
    const int arow = lane & 15, khalf = (lane >> 4) * 8;

    gemm_load_chunk(sbase, 0, m0, n0, tid, Ah, Al, Bh, Bl);

    for (int kc = 0; kc < HH / 32; ++kc) {
        if (kc + 1 < HH / 32) {
            gemm_load_chunk(sbase + ((kc + 1) & 1) * GQ_STAGE, (kc + 1) * 32, m0, n0, tid,
                            Ah, Al, Bh, Bl);
            cp_wait<1>();
        } else {
            cp_wait<0>();
        }
        __syncthreads();

        const uint32_t st = sbase + (kc & 1) * GQ_STAGE;
#pragma unroll
        for (int ks = 0; ks < 2; ++ks) {
            const int kb = (ks * 16 + khalf) * 2;
            uint32_t ah[4][4], al[4][4];
#pragma unroll
            for (int mi = 0; mi < 4; ++mi) {
                const uint32_t roff = (m_w + mi * 16 + arow) * GQ_ROWB + kb;
                ldm_x4(ah[mi][0], ah[mi][1], ah[mi][2], ah[mi][3], st + GQ_AH + roff);
                ldm_x4(al[mi][0], al[mi][1], al[mi][2], al[mi][3], st + GQ_AL + roff);
            }
            uint32_t bh[8][2], bl[8][2];
#pragma unroll
            for (int nf = 0; nf < 4; ++nf) {
                const uint32_t roff = (n_w + nf * 16 + arow) * GQ_ROWB + kb;
                uint32_t r0, r1, r2, r3;
                ldm_x4(r0, r1, r2, r3, st + GQ_BH + roff);
                bh[2 * nf][0] = r0; bh[2 * nf][1] = r2;
                bh[2 * nf + 1][0] = r1; bh[2 * nf + 1][1] = r3;
                ldm_x4(r0, r1, r2, r3, st + GQ_BL + roff);
                bl[2 * nf][0] = r0; bl[2 * nf][1] = r2;
                bl[2 * nf + 1][0] = r1; bl[2 * nf + 1][1] = r3;
            }
#pragma unroll
            for (int mi = 0; mi < 4; ++mi)
#pragma unroll
                for (int nj = 0; nj < 8; ++nj) {
                    mma16816(acc[mi][nj], ah[mi], bh[nj]);
                    mma16816(acc[mi][nj], ah[mi], bl[nj]);
                    mma16816(acc[mi][nj], al[mi], bh[nj]);
                }
        }
        __syncthreads();
    }
}

// ---- merged QKV GEMM: z selects weight; output scatter bf16 hi/lo [B,NH,S,HD] ----
__global__ void __launch_bounds__(256, 1) gemm_qkv(
    const __nv_bfloat16* __restrict__ Ah, const __nv_bfloat16* __restrict__ Al,
    const __nv_bfloat16* __restrict__ Bh0, const __nv_bfloat16* __restrict__ Bl0,
    const __nv_bfloat16* __restrict__ Bh1, const __nv_bfloat16* __restrict__ Bl1,
    const __nv_bfloat16* __restrict__ Bh2, const __nv_bfloat16* __restrict__ Bl2,
    const float* __restrict__ bias0, const float* __restrict__ bias1,
    const float* __restrict__ bias2,
    __nv_bfloat16* __restrict__ Ch0, __nv_bfloat16* __restrict__ Cl0,
    __nv_bfloat16* __restrict__ Ch1, __nv_bfloat16* __restrict__ Cl1,
    __nv_bfloat16* __restrict__ Ch2, __nv_bfloat16* __restrict__ Cl2)
{
    extern __shared__ char sm8[];
    const uint32_t sbase = smem_u32(sm8);
    const int tid = threadIdx.x;
    const int z = blockIdx.z;
    const __nv_bfloat16* Bh = (z == 0) ? Bh0 : (z == 1) ? Bh1 : Bh2;
    const __nv_bfloat16* Bl = (z == 0) ? Bl0 : (z == 1) ? Bl1 : Bl2;
    const float* bias = (z == 0) ? bias0 : (z == 1) ? bias1 : bias2;
    __nv_bfloat16* Ch = (z == 0) ? Ch0 : (z == 1) ? Ch1 : Ch2;
    __nv_bfloat16* Cl = (z == 0) ? Cl0 : (z == 1) ? Cl1 : Cl2;
    const float alpha = (z == 0) ? 0.08838834764831845f : 1.f;

    const int m0 = blockIdx.y * 256, n0 = blockIdx.x * 128;

    float acc[4][8][4];
#pragma unroll
    for (int i = 0; i < 4; i++)
#pragma unroll
        for (int j = 0; j < 8; j++)
#pragma unroll
            for (int q = 0; q < 4; q++) acc[i][j][q] = 0.f;

    gemm_core(sbase, m0, n0, tid, Ah, Al, Bh, Bl, acc);

    const int wid = tid >> 5, lane = tid & 31;
    const int m_w = (wid >> 1) * 64, n_w = (wid & 1) * 64;
    const int g = lane >> 2, qn = (lane & 3) * 2;
#pragma unroll
    for (int mi = 0; mi < 4; ++mi) {
#pragma unroll
        for (int h = 0; h < 2; ++h) {
            const int row = m0 + m_w + mi * 16 + g + h * 8;
            const int b_ = row >> 11, s_ = row & (SS - 1);
            const size_t base = ((size_t)((b_ * NHD + blockIdx.x) * SS + s_)) * HDD;
#pragma unroll
            for (int nf = 0; nf < 8; ++nf) {
                const int col = n_w + nf * 8 + qn;
                const float v0 = alpha * (acc[mi][nf][h * 2 + 0] + bias[n0 + col]);
                const float v1 = alpha * (acc[mi][nf][h * 2 + 1] + bias[n0 + col + 1]);
                const float r0f = v0 - __bfloat162float(__float2bfloat16(v0));
                const float r1f = v1 - __bfloat162float(__float2bfloat16(v1));
                *(uint32_t*)(Ch + base + col) = pack_bf16(v0, v1);
                *(uint32_t*)(Cl + base + col) = pack_bf16(r0f, r1f);
            }
        }
    }
}

// ---- O-projection GEMM: fp32 row-major out ----
__global__ void __launch_bounds__(256, 1) gemm_out(
    const __nv_bfloat16* __restrict__ Ah, const __nv_bfloat16* __restrict__ Al,
    const __nv_bfloat16* __restrict__ Bh, const __nv_bfloat16* __restrict__ Bl,
    const float* __restrict__ bias, float* __restrict__ C)
{
    extern __shared__ char sm8[];
    const uint32_t sbase = smem_u32(sm8);
    const int tid = threadIdx.x;
    const int m0 = blockIdx.y * 256, n0 = blockIdx.x * 128;

    float acc[4][8][4];
#pragma unroll
    for (int i = 0; i < 4; i++)
#pragma unroll
        for (int j = 0; j < 8; j++)
#pragma unroll
            for (int q = 0; q < 4; q++) acc[i][j][q] = 0.f;

    gemm_core(sbase, m0, n0, tid, Ah, Al, Bh, Bl, acc);

    const int wid = tid >> 5, lane = tid & 31;
    const int m_w = (wid >> 1) * 64, n_w = (wid & 1) * 64;
    const int g = lane >> 2, qn = (lane & 3) * 2;
#pragma unroll
    for (int mi = 0; mi < 4; ++mi) {
#pragma unroll
        for (int h = 0; h < 2; ++h) {
            const int row = m0 + m_w + mi * 16 + g + h * 8;
            float* dst = C + (size_t)row * HH + n0;
#pragma unroll
            for (int nf = 0; nf < 8; ++nf) {
                const int col = n_w + nf * 8 + qn;
                float2 ov;
                ov.x = acc[mi][nf][h * 2 + 0] + bias[n0 + col];
                ov.y = acc[mi][nf][h * 2 + 1] + bias[n0 + col + 1];
                *(float2*)(dst + col) = ov;
            }
        }
    }
}

// ======================= mma.sync flash attention (complement-of-window mask) =======================
// masked (excluded) iff 0 <= qi - kj < W.  Fully-masked 128-tiles: (i0>>7) - jt in {1,2,3}.
#define AT_STRIDE 272                    // bytes per smem row (128 bf16 + 16B pad)
#define AT_MAT    (128 * AT_STRIDE)      // 34816
#define AT_SMEM   (6 * AT_MAT)           // 208896

__device__ __forceinline__ void attn_load(uint32_t dst, const __nv_bfloat16* __restrict__ g,
                                          int row0, int tid)
{
    const __nv_bfloat16* gp = g + (size_t)row0 * HDD;
#pragma unroll
    for (int i = 0; i < 8; i++) {
        const int idx = tid + i * 256;
        const int r = idx >> 4, c = idx & 15;
        cp_async16(dst + r * AT_STRIDE + c * 16, gp + r * HDD + c * 8);
    }
}

__global__ void __launch_bounds__(256) attn_mma()
{
    extern __shared__ char smx[];
    const uint32_t sb = smem_u32(smx);
    const uint32_t Qh = sb,              Ql = sb + 1 * AT_MAT;
    const uint32_t Kh = sb + 2 * AT_MAT, Kl = sb + 3 * AT_MAT;
    const uint32_t Vh = sb + 4 * AT_MAT, Vl = sb + 5 * AT_MAT;

    const int i0 = blockIdx.x * 128;
    const int head = blockIdx.y;
    const int b = blockIdx.z;
    const size_t hb = (size_t)(b * NHD + head) * SS * HDD;
    const __nv_bfloat16 *qhB = g_qh + hb, *qlB = g_ql + hb;
    const __nv_bfloat16 *khB = g_kh + hb, *klB = g_kl + hb;
    const __nv_bfloat16 *vhB = g_vh + hb, *vlB = g_vl + hb;

    const int tid = threadIdx.x, wid = tid >> 5, lane = tid & 31;
    const int arow = lane & 15, khalf16 = (lane >> 4) * 16;   // byte offset half
    const int g = lane >> 2, q = lane & 3;
    const int row0 = i0 + wid * 16 + g;            // second row = row0 + 8

    // list of non-fully-masked key tiles
    int tiles[16]; int nt = 0;
    const int bi = i0 >> 7;
#pragma unroll
    for (int jt = 0; jt < 16; jt++) {
        const int d = bi - jt;
        if (d != 1 && d != 2 && d != 3) tiles[nt++] = jt;
    }

    // prologue loads: Q + K(t0) in group 0; V(t0) in group 1
    attn_load(Qh, qhB, i0, tid);
    attn_load(Ql, qlB, i0, tid);
    attn_load(Kh, khB, tiles[0] * 128, tid);
    attn_load(Kl, klB, tiles[0] * 128, tid);
    cp_commit();
    attn_load(Vh, vhB, tiles[0] * 128, tid);
    attn_load(Vl, vlB, tiles[0] * 128, tid);
    cp_commit();

    float o[16][4];
#pragma unroll
    for (int t = 0; t < 16; t++)
#pragma unroll
        for (int c = 0; c < 4; c++) o[t][c] = 0.f;
    float m0 = NEG_INF, m1 = NEG_INF, l0 = 0.f, l1 = 0.f;

    for (int ti = 0; ti < nt; ti++) {
        const int j0 = tiles[ti] * 128;

        cp_wait<1>();          // K(ti) (+Q) ready; V(ti) may still be in flight
        __syncthreads();

        // ---- S = Q K^T (3-term split) ----
        float s[16][4];
#pragma unroll
        for (int t = 0; t < 16; t++)
#pragma unroll
            for (int c = 0; c < 4; c++) s[t][c] = 0.f;

#pragma unroll
        for (int ks = 0; ks < 8; ks++) {
            const uint32_t kb = ks * 32 + khalf16;
            uint32_t qh4[4], ql4[4];
            const uint32_t aoff = (wid * 16 + arow) * AT_STRIDE + kb;
            ldm_x4(qh4[0], qh4[1], qh4[2], qh4[3], Qh + aoff);
            ldm_x4(ql4[0], ql4[1], ql4[2], ql4[3], Ql + aoff);
#pragma unroll
            for (int nf = 0; nf < 8; nf++) {
                const uint32_t roff = (nf * 16 + arow) * AT_STRIDE + kb;
                uint32_t r0, r1, r2, r3, u0, u1, u2, u3;
                ldm_x4(r0, r1, r2, r3, Kh + roff);
                ldm_x4(u0, u1, u2, u3, Kl + roff);
                uint32_t bh0[2] = {r0, r2}, bh1[2] = {r1, r3};
                uint32_t bl0[2] = {u0, u2}, bl1[2] = {u1, u3};
                mma16816(s[2 * nf], qh4, bh0);
                mma16816(s[2 * nf], qh4, bl0);
                mma16816(s[2 * nf], ql4, bh0);
                mma16816(s[2 * nf + 1], qh4, bh1);
                mma16816(s[2 * nf + 1], qh4, bl1);
                mma16816(s[2 * nf + 1], ql4, bh1);
            }
        }

        // ---- mask + online softmax (warp-local; rows row0, row0+8) ----
#pragma unroll
        for (int t = 0; t < 16; t++) {
            const int kj = j0 + 8 * t + 2 * q;
#pragma unroll
            for (int c = 0; c < 4; c++) {
                const int qi = (c < 2) ? row0 : row0 + 8;
                const int dl = qi - (kj + (c & 1));
                if (dl >= 0 && dl < WW) s[t][c] = NEG_INF;
            }
        }
        float rm0 = NEG_INF, rm1 = NEG_INF;
#pragma unroll
        for (int t = 0; t < 16; t++) {
            rm0 = fmaxf(rm0, fmaxf(s[t][0], s[t][1]));
            rm1 = fmaxf(rm1, fmaxf(s[t][2], s[t][3]));
        }
        rm0 = fmaxf(rm0, __shfl_xor_sync(0xffffffffu, rm0, 1));
        rm0 = fmaxf(rm0, __shfl_xor_sync(0xffffffffu, rm0, 2));
        rm1 = fmaxf(rm1, __shfl_xor_sync(0xffffffffu, rm1, 1));
        rm1 = fmaxf(rm1, __shfl_xor_sync(0xffffffffu, rm1, 2));
        const float mn0 = fmaxf(m0, rm0), mn1 = fmaxf(m1, rm1);
        const float c0 = (m0 == mn0) ? 1.f : __expf(m0 - mn0);
        const float c1 = (m1 == mn1) ? 1.f : __expf(m1 - mn1);
        float sum0 = 0.f, sum1 = 0.f;
#pragma unroll
        for (int t = 0; t < 16; t++) {
#pragma unroll
            for (int c = 0; c < 4; c++) {
                const float sv = s[t][c];
                const float mn = (c < 2) ? mn0 : mn1;
                const float p = (sv == NEG_INF) ? 0.f : __expf(sv - mn);
                s[t][c] = p;
                if (c < 2) sum0 += p; else sum1 += p;
            }
        }
        sum0 += __shfl_xor_sync(0xffffffffu, sum0, 1);
        sum0 += __shfl_xor_sync(0xffffffffu, sum0, 2);
        sum1 += __shfl_xor_sync(0xffffffffu, sum1, 1);
        sum1 += __shfl_xor_sync(0xffffffffu, sum1, 2);
        l0 = l0 * c0 + sum0; m0 = mn0;
        l1 = l1 * c1 + sum1; m1 = mn1;
#pragma unroll
        for (int t = 0; t < 16; t++) {
            o[t][0] *= c0; o[t][1] *= c0; o[t][2] *= c1; o[t][3] *= c1;
        }

        __syncthreads();       // all warps done reading K
        if (ti + 1 < nt) {
            const int jn = tiles[ti + 1] * 128;
            attn_load(Kh, khB, jn, tid);
            attn_load(Kl, klB, jn, tid);
        }
        cp_commit();           // K(ti+1) group (possibly empty)

        cp_wait<1>();          // V(ti) ready (pending: K(ti+1))
        __syncthreads();

        // ---- O += P V (3-term split; V fragments via ldmatrix.trans) ----
#pragma unroll
        for (int u = 0; u < 8; u++) {
            uint32_t ph[4], pl[4];
            {
                const float p00 = s[2 * u][0],     p01 = s[2 * u][1];
                const float p02 = s[2 * u][2],     p03 = s[2 * u][3];
                const float p10 = s[2 * u + 1][0], p11 = s[2 * u + 1][1];
                const float p12 = s[2 * u + 1][2], p13 = s[2 * u + 1][3];
                ph[0] = pack_bf16(p00, p01);
                ph[1] = pack_bf16(p02, p03);
                ph[2] = pack_bf16(p10, p11);
                ph[3] = pack_bf16(p12, p13);
                pl[0] = pack_bf16(p00 - __bfloat162float(__float2bfloat16(p00)),
                                  p01 - __bfloat162float(__float2bfloat16(p01)));
                pl[1] = pack_bf16(p02 - __bfloat162float(__float2bfloat16(p02)),
                                  p03 - __bfloat162float(__float2bfloat16(p03)));
                pl[2] = pack_bf16(p10 - __bfloat162float(__float2bfloat16(p10)),
                                  p11 - __bfloat162float(__float2bfloat16(p11)));
                pl[3] = pack_bf16(p12 - __bfloat162float(__float2bfloat16(p12)),
                                  p13 - __bfloat162float(__float2bfloat16(p13)));
            }
#pragma unroll
            for (int dp = 0; dp < 8; dp++) {
                const uint32_t roff = (u * 16 + arow) * AT_STRIDE + dp * 32 + khalf16;
                uint32_t r0, r1, r2, r3, u0, u1, u2, u3;
                ldm_x4t(r0, r1, r2, r3, Vh + roff);
                ldm_x4t(u0, u1, u2, u3, Vl + roff);
                uint32_t bvh0[2] = {r0, r1}, bvh1[2] = {r2, r3};
                uint32_t bvl0[2] = {u0, u1}, bvl1[2] = {u2, u3};
                mma16816(o[2 * dp], ph, bvh0);
                mma16816(o[2 * dp], ph, bvl0);
                mma16816(o[2 * dp], pl, bvh0);
                mma16816(o[2 * dp + 1], ph, bvh1);
                mma16816(o[2 * dp + 1], ph, bvl1);
                mma16816(o[2 * dp + 1], pl, bvh1);
            }
        }

        __syncthreads();       // all warps done reading V
        if (ti + 1 < nt) {
            const int jn = tiles[ti + 1] * 128;
            attn_load(Vh, vhB, jn, tid);
            attn_load(Vl, vlB, jn, tid);
        }
        cp_commit();           // V(ti+1) group (possibly empty)
    }

    // ---- epilogue: normalize, split hi/lo, write [B,S,NH,HD] ----
    const float inv0 = 1.f / l0, inv1 = 1.f / l1;
    const size_t base0 = ((size_t)(b * SS + row0) * NHD + head) * HDD;
    const size_t base1 = base0 + (size_t)8 * NHD * HDD;
#pragma unroll
    for (int t = 0; t < 16; t++) {
        const int d = 8 * t + 2 * q;
        const float f0 = o[t][0] * inv0, f1 = o[t][1] * inv0;
        const float f2 = o[t][2] * inv1, f3 = o[t][3] * inv1;
        *(uint32_t*)(g_aoh + base0 + d) = pack_bf16(f0, f1);
        *(uint32_t*)(g_aol + base0 + d) =
            pack_bf16(f0 - __bfloat162float(__float2bfloat16(f0)),
                      f1 - __bfloat162float(__float2bfloat16(f1)));
        *(uint32_t*)(g_aoh + base1 + d) = pack_bf16(f2, f3);
        *(uint32_t*)(g_aol + base1 + d) =
            pack_bf16(f2 - __bfloat162float(__float2bfloat16(f2)),
                      f3 - __bfloat162float(__float2bfloat16(f3)));
    }
}

// ======================= launch =======================
extern "C" void kernel_launch(void* const* d_in, const int* in_sizes, int n_in,
                              void* d_out, int out_size)
{
    (void)in_sizes; (void)n_in; (void)out_size;
    const float* x   = (const float*)d_in[0];
    const float* lns = (const float*)d_in[1];
    const float* lnb = (const float*)d_in[2];
    const float* wq  = (const float*)d_in[3];
    const float* bq  = (const float*)d_in[4];
    const float* wk  = (const float*)d_in[5];
    const float* bk  = (const float*)d_in[6];
    const float* wv  = (const float*)d_in[7];
    const float* bv  = (const float*)d_in[8];
    const float* wo  = (const float*)d_in[9];
    const float* bo  = (const float*)d_in[10];
    float* out = (float*)d_out;

    __nv_bfloat16 *pyh, *pyl, *pwqh, *pwql, *pwkh, *pwkl, *pwvh, *pwvl, *pwoh, *pwol;
    __nv_bfloat16 *pqh, *pql, *pkh, *pkl, *pvh, *pvl, *paoh, *paol;
    cudaGetSymbolAddress((void**)&pyh, g_yh);   cudaGetSymbolAddress((void**)&pyl, g_yl);
    cudaGetSymbolAddress((void**)&pwqh, g_wqh); cudaGetSymbolAddress((void**)&pwql, g_wql);
    cudaGetSymbolAddress((void**)&pwkh, g_wkh); cudaGetSymbolAddress((void**)&pwkl, g_wkl);
    cudaGetSymbolAddress((void**)&pwvh, g_wvh); cudaGetSymbolAddress((void**)&pwvl, g_wvl);
    cudaGetSymbolAddress((void**)&pwoh, g_woh); cudaGetSymbolAddress((void**)&pwol, g_wol);
    cudaGetSymbolAddress((void**)&pqh, g_qh);   cudaGetSymbolAddress((void**)&pql, g_ql);
    cudaGetSymbolAddress((void**)&pkh, g_kh);   cudaGetSymbolAddress((void**)&pkl, g_kl);
    cudaGetSymbolAddress((void**)&pvh, g_vh);   cudaGetSymbolAddress((void**)&pvl, g_vl);
    cudaGetSymbolAddress((void**)&paoh, g_aoh); cudaGetSymbolAddress((void**)&paol, g_aol);

    ln_kernel<<<BSZ, 256>>>(x, lns, lnb, pyh, pyl);

    wsplit_all<<<dim3(HH / 32, HH / 32, 4), 256>>>(
        wq, wk, wv, wo, pwqh, pwql, pwkh, pwkl, pwvh, pwvl, pwoh, pwol);

    cudaFuncSetAttribute(gemm_qkv, cudaFuncAttributeMaxDynamicSharedMemorySize, GQ_SMEM);
    cudaFuncSetAttribute(gemm_out, cudaFuncAttributeMaxDynamicSharedMemorySize, GQ_SMEM);

    gemm_qkv<<<dim3(HH / 128, BSZ / 256, 3), 256, GQ_SMEM>>>(
        pyh, pyl, pwqh, pwql, pwkh, pwkl, pwvh, pwvl,
        bq, bk, bv, pqh, pql, pkh, pkl, pvh, pvl);

    cudaFuncSetAttribute(attn_mma, cudaFuncAttributeMaxDynamicSharedMemorySize, AT_SMEM);
    attn_mma<<<dim3(SS / 128, NHD, BB), 256, AT_SMEM>>>();

    gemm_out<<<dim3(HH / 128, BSZ / 256), 256, GQ_SMEM>>>(paoh, paol, pwoh, pwol, bo, out);
}